// round 3
// baseline (speedup 1.0000x reference)
#include <cuda_runtime.h>

#define NMAX 64
#define OUTD 224
#define HW   50176          // 224*224
#define FC   2048
#define FHW  49             // 7*7
#define RMAX 32             // max runs/row (true bound ~4: piecewise-linear rows)
#define NRUNS (OUTD * RMAX) // 7168
#define NSLICE 4
#define ROWS_PER (OUTD / NSLICE)  // 56

// global scratch (no allocations allowed)
__device__ float    d_part[NMAX * NSLICE * FHW];
__device__ unsigned d_mask[NMAX * OUTD * 7];
__device__ __align__(16) float2 d_tr[NMAX * OUTD];   // per-(n,row): (x0 bits, wx)
__device__ __align__(16) float2 d_tc[NMAX * OUTD];   // per-(n,col): (y0 bits, wy)

// ---------------- union-find over run ids in shared memory ----------------
__device__ __forceinline__ int uf_find(int* P, int i) {
    int p = P[i];
    while (p != i) {
        int gp = P[p];
        if (gp != p) P[i] = gp;   // path halving (benign race)
        i = p; p = gp;
    }
    return i;
}

__device__ __forceinline__ void uf_union(int* P, int a, int b) {
    int ra = uf_find(P, a), rb = uf_find(P, b);
    while (ra != rb) {
        if (ra < rb) { int t = ra; ra = rb; rb = t; }
        int old = atomicCAS(&P[ra], ra, rb);   // link larger root under smaller
        if (old == ra) break;
        ra = uf_find(P, old);
        rb = uf_find(P, rb);
    }
}

// ---------------- kernel 1: per-slice channel-max of |feat| ----------------
// grid (NSLICE, N), block 784: t = cg*49 + p, addr = base + t + 784k (contiguous)
__global__ __launch_bounds__(784) void k_featmax(const float* __restrict__ feat)
{
    __shared__ float sP[16 * FHW];
    const int n = blockIdx.y, s = blockIdx.x;
    const int t = threadIdx.x;
    const float* base = feat + (size_t)n * (FC * FHW) + s * 512 * FHW + t;
    float m = 0.f;
    #pragma unroll 8
    for (int k = 0; k < 32; k++)
        m = fmaxf(m, fabsf(base[k * 16 * FHW]));
    sP[t] = m;
    __syncthreads();
    if (t < FHW) {
        float mm = sP[t];
        #pragma unroll
        for (int j = 1; j < 16; j++) mm = fmaxf(mm, sP[j * FHW + t]);
        d_part[(n * NSLICE + s) * FHW + t] = mm;
    }
}

// ---------------- kernel 2: normalize + bilinear upsample + bitmask ----------------
// grid (NSLICE, N), block 1024; CTA s handles rows [s*56, s*56+56)
__global__ __launch_bounds__(1024) void k_upsample(float* __restrict__ outHeat)
{
    __shared__ float sH[FHW];
    __shared__ int   sX0[OUTD], sX1[OUTD];
    __shared__ float sWt[OUTD];
    __shared__ float sMn, sMx;

    const int n = blockIdx.y, s = blockIdx.x;
    const int tid = threadIdx.x;

    if (tid < FHW) {
        const float* pp = d_part + n * NSLICE * FHW + tid;
        float m = pp[0];
        m = fmaxf(m, pp[FHW]);
        m = fmaxf(m, pp[2 * FHW]);
        m = fmaxf(m, pp[3 * FHW]);
        sH[tid] = m;
    }
    if (tid >= 64 && tid < 64 + OUTD) {   // tables (exact reference arithmetic)
        int i = tid - 64;
        float g  = (float)i / 223.0f;
        float xs = __fmul_rn(g, 6.0f);
        int x0 = (int)floorf(xs);
        x0 = min(max(x0, 0), 6);
        sX0[i] = x0;
        sX1[i] = min(x0 + 1, 6);
        sWt[i] = __fsub_rn(xs, (float)x0);
    }
    __syncthreads();
    if (tid == 0) {
        float mn = sH[0], mx = sH[0];
        for (int j = 1; j < FHW; j++) { mn = fminf(mn, sH[j]); mx = fmaxf(mx, sH[j]); }
        sMn = mn; sMx = mx;
    }
    __syncthreads();
    if (tid < FHW) sH[tid] = (sH[tid] - sMn) / (sMx - sMn);
    __syncthreads();

    const int r0 = s * ROWS_PER;
    float*    oh = outHeat + (size_t)n * HW + r0 * OUTD;
    unsigned* mk = d_mask + n * OUTD * 7 + r0 * 7;
    const int TOT = ROWS_PER * OUTD;   // 12544; warps never straddle rows (224%32==0)
    for (int o = tid; o < TOT; o += 1024) {
        int r = r0 + o / OUTD, c = o % OUTD;
        int x0 = sX0[r], x1 = sX1[r]; float wx = sWt[r];
        int y0 = sX0[c], y1 = sX1[c]; float wy = sWt[c];
        float v00 = sH[x0 * 7 + y0], v01 = sH[x0 * 7 + y1];
        float v10 = sH[x1 * 7 + y0], v11 = sH[x1 * 7 + y1];
        float iwy = __fsub_rn(1.f, wy);
        float a = __fadd_rn(__fmul_rn(iwy, v00), __fmul_rn(wy, v01));
        float b = __fadd_rn(__fmul_rn(iwy, v10), __fmul_rn(wy, v11));
        float v = __fadd_rn(__fmul_rn(__fsub_rn(1.f, wx), a), __fmul_rn(wx, b));
        oh[o] = v;
        unsigned m = __ballot_sync(0xffffffffu, v > 0.7f);
        if ((tid & 31) == 0) mk[o >> 5] = m;
    }
}

// ---------------- kernel 3: run-based CCL + bbox + crop tables (all-shared) ----------------
__global__ __launch_bounds__(256) void k_ccl(float* __restrict__ outCoords)
{
    extern __shared__ int S[];     // sSE[NRUNS], P[NRUNS], cnt[NRUNS]
    int* sSE = S;
    int* P   = S + NRUNS;
    int* cnt = S + 2 * NRUNS;

    __shared__ unsigned sMask[OUTD * 7];
    __shared__ int  sRunCnt[OUTD];
    __shared__ int  sBC[8], sBR[8];
    __shared__ int  sBest, sBestCnt, sRmin, sRmax, sCmin, sCmax;
    __shared__ int4 sBox;

    const int n = blockIdx.x;
    const int tid = threadIdx.x;

    for (int w = tid; w < OUTD * 7; w += 256) sMask[w] = d_mask[n * OUTD * 7 + w];
    for (int g = tid; g < NRUNS; g += 256) { P[g] = g; cnt[g] = 0; }
    if (tid == 0) { sRmin = HW; sRmax = -1; sCmin = HW; sCmax = -1; }
    __syncthreads();

    // Phase D: per-row run extraction
    if (tid < OUTD) {
        int r = tid, base = r * 7, cntR = 0, pos = 0;
        while (pos < 224 && cntR < RMAX) {
            int w = pos >> 5;
            unsigned m = sMask[base + w] & (0xffffffffu << (pos & 31));
            while (m == 0 && ++w < 7) m = sMask[base + w];
            if (m == 0) break;
            int start = (w << 5) + __ffs(m) - 1;
            unsigned inv = (~sMask[base + w]) & (0xffffffffu << (start & 31));
            int w2 = w;
            while (inv == 0 && ++w2 < 7) inv = ~sMask[base + w2];
            int end = (w2 == 7) ? 223 : ((w2 << 5) + __ffs(inv) - 2);
            sSE[r * RMAX + cntR] = (start << 16) | end;
            cntR++;
            pos = end + 2;
        }
        sRunCnt[r] = cntR;
    }
    __syncthreads();

    // Phase E: union overlapping runs in adjacent rows (8-connectivity)
    if (tid < OUTD - 1) {
        int r = tid;
        int ca = sRunCnt[r], cb = sRunCnt[r + 1];
        int i = 0, j = 0;
        while (i < ca && j < cb) {
            int A = sSE[r * RMAX + i];        int a0 = A >> 16, a1 = A & 0xffff;
            int B = sSE[(r + 1) * RMAX + j];  int b0 = B >> 16, b1 = B & 0xffff;
            if (b0 <= a1 + 1 && a0 <= b1 + 1)
                uf_union(P, r * RMAX + i, (r + 1) * RMAX + j);
            if (a1 <= b1) i++; else j++;
        }
    }
    __syncthreads();

    // Phase F: pixel counts per component (shared atomics)
    for (int g = tid; g < NRUNS; g += 256) {
        int row = g >> 5, slot = g & (RMAX - 1);
        if (slot < sRunCnt[row]) {
            int A = sSE[g];
            atomicAdd(&cnt[uf_find(P, g)], (A & 0xffff) - (A >> 16) + 1);
        }
    }
    __syncthreads();

    // Phase G: argmax (count, tie -> smallest root id == smallest min-pixel-label)
    {
        int bc = 0, br = 0x7fffffff;
        for (int g = tid; g < NRUNS; g += 256) {
            int row = g >> 5, slot = g & (RMAX - 1);
            if (slot < sRunCnt[row]) {
                int cc = cnt[g];
                if (cc > bc || (cc == bc && g < br)) { bc = cc; br = g; }
            }
        }
        #pragma unroll
        for (int off = 16; off; off >>= 1) {
            int oc  = __shfl_down_sync(0xffffffffu, bc, off);
            int orr = __shfl_down_sync(0xffffffffu, br, off);
            if (oc > bc || (oc == bc && orr < br)) { bc = oc; br = orr; }
        }
        if ((tid & 31) == 0) { sBC[tid >> 5] = bc; sBR[tid >> 5] = br; }
        __syncthreads();
        if (tid == 0) {
            bc = sBC[0]; br = sBR[0];
            for (int j = 1; j < 8; j++) {
                if (sBC[j] > bc || (sBC[j] == bc && sBR[j] < br)) { bc = sBC[j]; br = sBR[j]; }
            }
            sBest = br; sBestCnt = bc;
        }
    }
    __syncthreads();

    // Phase H: bbox of largest component
    if (sBestCnt > 0) {
        int best = sBest;
        int rmin = HW, rmax = -1, cmin = HW, cmax = -1;
        for (int g = tid; g < NRUNS; g += 256) {
            int row = g >> 5, slot = g & (RMAX - 1);
            if (slot < sRunCnt[row] && uf_find(P, g) == best) {
                int A = sSE[g];
                rmin = min(rmin, row); rmax = max(rmax, row);
                cmin = min(cmin, A >> 16); cmax = max(cmax, A & 0xffff);
            }
        }
        if (rmax >= 0) {
            atomicMin(&sRmin, rmin); atomicMax(&sRmax, rmax);
            atomicMin(&sCmin, cmin); atomicMax(&sCmax, cmax);
        }
    }
    __syncthreads();

    if (tid == 0) {
        int xmin = sRmin, xmax = sRmax, ymin = sCmin, ymax = sCmax;
        if (sBestCnt <= 0 || xmax < 0) { xmin = 0; ymin = 0; xmax = OUTD - 1; ymax = OUTD - 1; }
        sBox = make_int4(xmin, xmax, ymin, ymax);
        float* co = outCoords + n * 4;
        co[0] = (float)ymin; co[1] = (float)xmin;    // torch order [ymin,xmin,ymax,xmax]
        co[2] = (float)ymax; co[3] = (float)xmax;
    }
    __syncthreads();

    // Phase I: crop interpolation tables
    if (tid < OUTD) {
        int4 bx = sBox;
        int i = tid;
        float g = (float)i / 223.0f;
        int Lx = max(bx.y - bx.x, 1);
        float xs = __fadd_rn((float)bx.x, __fmul_rn(g, (float)(Lx - 1)));
        int x0 = min(max((int)floorf(xs), 0), 223);
        d_tr[n * OUTD + i] = make_float2(__int_as_float(x0), __fsub_rn(xs, (float)x0));
        int Ly = max(bx.w - bx.z, 1);
        float ys = __fadd_rn((float)bx.z, __fmul_rn(g, (float)(Ly - 1)));
        int y0 = min(max((int)floorf(ys), 0), 223);
        d_tc[n * OUTD + i] = make_float2(__int_as_float(y0), __fsub_rn(ys, (float)y0));
    }
}

// ---------------- kernel 4: crop + resize via shared source rows ----------------
// grid (224, N): block = one output row, all 3 channels
__global__ __launch_bounds__(224) void k_crop(const float* __restrict__ x,
                                              float* __restrict__ out)
{
    __shared__ float sRow[6][OUTD];   // [ch*2 + {top,bot}]
    const int r = blockIdx.x, n = blockIdx.y;
    const int tid = threadIdx.x;

    float2 tr = d_tr[n * OUTD + r];
    int x0 = __float_as_int(tr.x);
    int x1 = min(x0 + 1, 223);
    float wx = tr.y;

    const float* img = x + (size_t)n * 3 * HW;
    #pragma unroll
    for (int ch = 0; ch < 3; ch++) {
        sRow[ch * 2 + 0][tid] = __ldg(&img[ch * HW + x0 * OUTD + tid]);
        sRow[ch * 2 + 1][tid] = __ldg(&img[ch * HW + x1 * OUTD + tid]);
    }
    float2 tc = d_tc[n * OUTD + tid];
    int y0 = __float_as_int(tc.x);
    int y1 = min(y0 + 1, 223);
    float wy = tc.y;
    __syncthreads();

    float iwy = __fsub_rn(1.f, wy), iwx = __fsub_rn(1.f, wx);
    float* o = out + (size_t)n * 3 * HW + r * OUTD + tid;
    #pragma unroll
    for (int ch = 0; ch < 3; ch++) {
        float v00 = sRow[ch * 2][y0],     v01 = sRow[ch * 2][y1];
        float v10 = sRow[ch * 2 + 1][y0], v11 = sRow[ch * 2 + 1][y1];
        float a = __fadd_rn(__fmul_rn(iwy, v00), __fmul_rn(wy, v01));
        float b = __fadd_rn(__fmul_rn(iwy, v10), __fmul_rn(wy, v11));
        o[ch * HW] = __fadd_rn(__fmul_rn(iwx, a), __fmul_rn(wx, b));
    }
}

// ---------------- launch ----------------
extern "C" void kernel_launch(void* const* d_in, const int* in_sizes, int n_in,
                              void* d_out, int out_size)
{
    const float* x    = (const float*)d_in[0];   // (N,3,224,224)
    const float* feat = (const float*)d_in[1];   // (N,2048,7,7)
    float* out = (float*)d_out;

    int N = in_sizes[0] / (3 * HW);
    if (N > NMAX) N = NMAX;

    float* outCrop   = out;
    float* outHeat   = out + (size_t)N * 3 * HW;
    float* outCoords = out + (size_t)N * 3 * HW + (size_t)N * HW;

    static int smemSet = 0;
    if (!smemSet) {
        cudaFuncSetAttribute(k_ccl, cudaFuncAttributeMaxDynamicSharedMemorySize,
                             3 * NRUNS * (int)sizeof(int));
        smemSet = 1;
    }

    k_featmax <<<dim3(NSLICE, N), 784>>>(feat);
    k_upsample<<<dim3(NSLICE, N), 1024>>>(outHeat);
    k_ccl     <<<N, 256, 3 * NRUNS * sizeof(int)>>>(outCoords);
    k_crop    <<<dim3(OUTD, N), OUTD>>>(x, outCrop);
}

// round 4
// speedup vs baseline: 1.6232x; 1.6232x over previous
#include <cuda_runtime.h>

#define NMAX 64
#define OUTD 224
#define HW   50176          // 224*224
#define FC   2048
#define FHW  49             // 7*7
#define RMAX 32             // max runs/row (true bound ~4: rows are piecewise-linear)
#define NRUNS (OUTD * RMAX) // 7168
#define NSLICE 4

// global scratch (no allocations allowed)
__device__ float d_part[NMAX * NSLICE * FHW];
__device__ __align__(16) float2 d_tr[NMAX * OUTD];   // per-(n,row): (x0 bits, wx)
__device__ __align__(16) float2 d_tc[NMAX * OUTD];   // per-(n,col): (y0 bits, wy)

// ---------------- union-find over run ids in shared memory ----------------
__device__ __forceinline__ int uf_find(int* P, int i) {
    int p = P[i];
    while (p != i) {
        int gp = P[p];
        if (gp != p) P[i] = gp;   // path halving (benign race)
        i = p; p = gp;
    }
    return i;
}

__device__ __forceinline__ void uf_union(int* P, int a, int b) {
    int ra = uf_find(P, a), rb = uf_find(P, b);
    while (ra != rb) {
        if (ra < rb) { int t = ra; ra = rb; rb = t; }
        int old = atomicCAS(&P[ra], ra, rb);   // link larger root under smaller
        if (old == ra) break;
        ra = uf_find(P, old);
        rb = uf_find(P, rb);
    }
}

// ---------------- kernel 1: per-slice channel-max of |feat| ----------------
// grid (NSLICE, N), block 784: t = cg*49 + p, addr = base + t + 784k (contiguous)
__global__ __launch_bounds__(784) void k_featmax(const float* __restrict__ feat)
{
    __shared__ float sP[16 * FHW];
    const int n = blockIdx.y, s = blockIdx.x;
    const int t = threadIdx.x;
    const float* base = feat + (size_t)n * (FC * FHW) + s * 512 * FHW + t;
    float m = 0.f;
    #pragma unroll 8
    for (int k = 0; k < 32; k++)
        m = fmaxf(m, fabsf(base[k * 16 * FHW]));
    sP[t] = m;
    __syncthreads();
    if (t < FHW) {
        float mm = sP[t];
        #pragma unroll
        for (int j = 1; j < 16; j++) mm = fmaxf(mm, sP[j * FHW + t]);
        d_part[(n * NSLICE + s) * FHW + t] = mm;
    }
}

// ---------------- kernel 2: normalize + upsample + mask + CCL + bbox + tables ----------------
// one CTA per image; everything after the 196-float read lives in shared memory
__global__ __launch_bounds__(1024, 1) void k_main(
    float* __restrict__ outHeat,
    float* __restrict__ outCoords)
{
    extern __shared__ int S[];     // sSE[NRUNS], P[NRUNS], cnt[NRUNS]  (86 KB)
    int* sSE = S;
    int* P   = S + NRUNS;
    int* cnt = S + 2 * NRUNS;

    __shared__ float sH[FHW];
    __shared__ int   sX0[OUTD], sX1[OUTD];
    __shared__ float sWt[OUTD];
    __shared__ unsigned sMask[OUTD * 7];
    __shared__ int   sRunCnt[OUTD];
    __shared__ float sMn, sMx;
    __shared__ int   sBC[32], sBR[32];
    __shared__ int   sBest, sBestCnt, sRmin, sRmax, sCmin, sCmax;
    __shared__ int4  sBox;

    const int n   = blockIdx.x;
    const int tid = threadIdx.x;

    // Phase B: gather partial maxes, interp tables, init UF state
    if (tid < FHW) {
        const float* pp = d_part + n * NSLICE * FHW + tid;
        float m = pp[0];
        m = fmaxf(m, pp[FHW]);
        m = fmaxf(m, pp[2 * FHW]);
        m = fmaxf(m, pp[3 * FHW]);
        sH[tid] = m;
    }
    if (tid >= 64 && tid < 64 + OUTD) {   // exact reference arithmetic
        int i = tid - 64;
        float g  = (float)i / 223.0f;
        float xs = __fmul_rn(g, 6.0f);
        int x0 = (int)floorf(xs);
        x0 = min(max(x0, 0), 6);
        sX0[i] = x0;
        sX1[i] = min(x0 + 1, 6);
        sWt[i] = __fsub_rn(xs, (float)x0);
    }
    for (int g = tid; g < NRUNS; g += 1024) { P[g] = g; cnt[g] = 0; }
    if (tid == 0) { sRmin = HW; sRmax = -1; sCmin = HW; sCmax = -1; }
    __syncthreads();
    if (tid == 0) {
        float mn = sH[0], mx = sH[0];
        for (int j = 1; j < FHW; j++) { mn = fminf(mn, sH[j]); mx = fmaxf(mx, sH[j]); }
        sMn = mn; sMx = mx;
    }
    __syncthreads();
    if (tid < FHW) sH[tid] = (sH[tid] - sMn) / (sMx - sMn);
    __syncthreads();

    // Phase C: bilinear upsample 7->224, write out_heatmap, ballot mask into shared
    float* oh = outHeat + (size_t)n * HW;
    for (int o = tid; o < HW; o += 1024) {         // 49 uniform iterations, full warps
        int r = o / OUTD, c = o % OUTD;
        int x0 = sX0[r], x1 = sX1[r]; float wx = sWt[r];
        int y0 = sX0[c], y1 = sX1[c]; float wy = sWt[c];
        float v00 = sH[x0 * 7 + y0], v01 = sH[x0 * 7 + y1];
        float v10 = sH[x1 * 7 + y0], v11 = sH[x1 * 7 + y1];
        float iwy = __fsub_rn(1.f, wy);
        float a = __fadd_rn(__fmul_rn(iwy, v00), __fmul_rn(wy, v01));
        float b = __fadd_rn(__fmul_rn(iwy, v10), __fmul_rn(wy, v11));
        float v = __fadd_rn(__fmul_rn(__fsub_rn(1.f, wx), a), __fmul_rn(wx, b));
        oh[o] = v;
        unsigned m = __ballot_sync(0xffffffffu, v > 0.7f);   // lane l <-> col bit
        if ((tid & 31) == 0) sMask[o >> 5] = m;              // 224 % 32 == 0: no straddle
    }
    __syncthreads();

    // Phase D: per-row run extraction
    if (tid < OUTD) {
        int r = tid, base = r * 7, cntR = 0, pos = 0;
        while (pos < 224 && cntR < RMAX) {
            int w = pos >> 5;
            unsigned m = sMask[base + w] & (0xffffffffu << (pos & 31));
            while (m == 0 && ++w < 7) m = sMask[base + w];
            if (m == 0) break;
            int start = (w << 5) + __ffs(m) - 1;
            unsigned inv = (~sMask[base + w]) & (0xffffffffu << (start & 31));
            int w2 = w;
            while (inv == 0 && ++w2 < 7) inv = ~sMask[base + w2];
            int end = (w2 == 7) ? 223 : ((w2 << 5) + __ffs(inv) - 2);
            sSE[r * RMAX + cntR] = (start << 16) | end;
            cntR++;
            pos = end + 2;
        }
        sRunCnt[r] = cntR;
    }
    __syncthreads();

    // Phase E: union overlapping runs in adjacent rows (8-connectivity)
    if (tid < OUTD - 1) {
        int r = tid;
        int ca = sRunCnt[r], cb = sRunCnt[r + 1];
        int i = 0, j = 0;
        while (i < ca && j < cb) {
            int A = sSE[r * RMAX + i];        int a0 = A >> 16, a1 = A & 0xffff;
            int B = sSE[(r + 1) * RMAX + j];  int b0 = B >> 16, b1 = B & 0xffff;
            if (b0 <= a1 + 1 && a0 <= b1 + 1)
                uf_union(P, r * RMAX + i, (r + 1) * RMAX + j);
            if (a1 <= b1) i++; else j++;
        }
    }
    __syncthreads();

    // Phase F: pixel counts per component (shared atomics)
    for (int g = tid; g < NRUNS; g += 1024) {
        int row = g >> 5, slot = g & (RMAX - 1);
        if (slot < sRunCnt[row]) {
            int A = sSE[g];
            atomicAdd(&cnt[uf_find(P, g)], (A & 0xffff) - (A >> 16) + 1);
        }
    }
    __syncthreads();

    // Phase G: argmax (count, tie -> smallest root id == smallest min-pixel-label)
    {
        int bc = 0, br = 0x7fffffff;
        for (int g = tid; g < NRUNS; g += 1024) {
            int row = g >> 5, slot = g & (RMAX - 1);
            if (slot < sRunCnt[row]) {
                int cc = cnt[g];
                if (cc > bc || (cc == bc && g < br)) { bc = cc; br = g; }
            }
        }
        #pragma unroll
        for (int off = 16; off; off >>= 1) {
            int oc  = __shfl_down_sync(0xffffffffu, bc, off);
            int orr = __shfl_down_sync(0xffffffffu, br, off);
            if (oc > bc || (oc == bc && orr < br)) { bc = oc; br = orr; }
        }
        if ((tid & 31) == 0) { sBC[tid >> 5] = bc; sBR[tid >> 5] = br; }
        __syncthreads();
        if (tid == 0) {
            bc = sBC[0]; br = sBR[0];
            for (int j = 1; j < 32; j++) {
                if (sBC[j] > bc || (sBC[j] == bc && sBR[j] < br)) { bc = sBC[j]; br = sBR[j]; }
            }
            sBest = br; sBestCnt = bc;
        }
    }
    __syncthreads();

    // Phase H: bbox of largest component
    if (sBestCnt > 0) {
        int best = sBest;
        int rmin = HW, rmax = -1, cmin = HW, cmax = -1;
        for (int g = tid; g < NRUNS; g += 1024) {
            int row = g >> 5, slot = g & (RMAX - 1);
            if (slot < sRunCnt[row] && uf_find(P, g) == best) {
                int A = sSE[g];
                rmin = min(rmin, row); rmax = max(rmax, row);
                cmin = min(cmin, A >> 16); cmax = max(cmax, A & 0xffff);
            }
        }
        if (rmax >= 0) {
            atomicMin(&sRmin, rmin); atomicMax(&sRmax, rmax);
            atomicMin(&sCmin, cmin); atomicMax(&sCmax, cmax);
        }
    }
    __syncthreads();

    if (tid == 0) {
        int xmin = sRmin, xmax = sRmax, ymin = sCmin, ymax = sCmax;
        if (sBestCnt <= 0 || xmax < 0) { xmin = 0; ymin = 0; xmax = OUTD - 1; ymax = OUTD - 1; }
        sBox = make_int4(xmin, xmax, ymin, ymax);
        float* co = outCoords + n * 4;
        co[0] = (float)ymin; co[1] = (float)xmin;    // torch order [ymin,xmin,ymax,xmax]
        co[2] = (float)ymax; co[3] = (float)xmax;
    }
    __syncthreads();

    // Phase I: crop interpolation tables
    if (tid < OUTD) {
        int4 bx = sBox;
        int i = tid;
        float g = (float)i / 223.0f;
        int Lx = max(bx.y - bx.x, 1);
        float xs = __fadd_rn((float)bx.x, __fmul_rn(g, (float)(Lx - 1)));
        int x0 = min(max((int)floorf(xs), 0), 223);
        d_tr[n * OUTD + i] = make_float2(__int_as_float(x0), __fsub_rn(xs, (float)x0));
        int Ly = max(bx.w - bx.z, 1);
        float ys = __fadd_rn((float)bx.z, __fmul_rn(g, (float)(Ly - 1)));
        int y0 = min(max((int)floorf(ys), 0), 223);
        d_tc[n * OUTD + i] = make_float2(__int_as_float(y0), __fsub_rn(ys, (float)y0));
    }
}

// ---------------- kernel 3: crop + align-corners bilinear resize (4 outputs/thread) ----------------
__device__ __forceinline__ float bilin1(const float* __restrict__ r0,
                                        const float* __restrict__ r1,
                                        float y0f, float wy, float wx)
{
    int y0 = __float_as_int(y0f);
    int y1 = min(y0 + 1, 223);
    float v00 = __ldg(&r0[y0]), v01 = __ldg(&r0[y1]);
    float v10 = __ldg(&r1[y0]), v11 = __ldg(&r1[y1]);
    float iwy = __fsub_rn(1.f, wy);
    float a = __fadd_rn(__fmul_rn(iwy, v00), __fmul_rn(wy, v01));
    float b = __fadd_rn(__fmul_rn(iwy, v10), __fmul_rn(wy, v11));
    return __fadd_rn(__fmul_rn(__fsub_rn(1.f, wx), a), __fmul_rn(wx, b));
}

__global__ void k_crop(const float* __restrict__ x, float* __restrict__ out, int total4)
{
    int idx = blockIdx.x * blockDim.x + threadIdx.x;
    if (idx >= total4) return;
    int c4 = idx % 56;                 // 4-col group
    int r  = (idx / 56) % OUTD;
    int nc = idx / (56 * OUTD);        // n*3 + ch
    int n  = nc / 3;
    int c0 = c4 * 4;

    float2 tr = d_tr[n * OUTD + r];
    int x0 = __float_as_int(tr.x);
    int x1 = min(x0 + 1, 223);
    float wx = tr.y;

    const float* img  = x + (size_t)nc * HW;
    const float* row0 = img + x0 * OUTD;
    const float* row1 = img + x1 * OUTD;

    const float4* tc4 = reinterpret_cast<const float4*>(d_tc + n * OUTD + c0);
    float4 ta = tc4[0];   // (y0f_a, wy_a, y0f_b, wy_b)
    float4 tb = tc4[1];   // (y0f_c, wy_c, y0f_d, wy_d)

    float4 res;
    res.x = bilin1(row0, row1, ta.x, ta.y, wx);
    res.y = bilin1(row0, row1, ta.z, ta.w, wx);
    res.z = bilin1(row0, row1, tb.x, tb.y, wx);
    res.w = bilin1(row0, row1, tb.z, tb.w, wx);

    *reinterpret_cast<float4*>(out + (size_t)nc * HW + r * OUTD + c0) = res;
}

// ---------------- launch ----------------
extern "C" void kernel_launch(void* const* d_in, const int* in_sizes, int n_in,
                              void* d_out, int out_size)
{
    const float* x    = (const float*)d_in[0];   // (N,3,224,224)
    const float* feat = (const float*)d_in[1];   // (N,2048,7,7)
    float* out = (float*)d_out;

    int N = in_sizes[0] / (3 * HW);
    if (N > NMAX) N = NMAX;

    float* outCrop   = out;
    float* outHeat   = out + (size_t)N * 3 * HW;
    float* outCoords = out + (size_t)N * 3 * HW + (size_t)N * HW;

    static int smemSet = 0;
    if (!smemSet) {
        cudaFuncSetAttribute(k_main, cudaFuncAttributeMaxDynamicSharedMemorySize,
                             3 * NRUNS * (int)sizeof(int));
        smemSet = 1;
    }

    k_featmax<<<dim3(NSLICE, N), 784>>>(feat);
    k_main   <<<N, 1024, 3 * NRUNS * sizeof(int)>>>(outHeat, outCoords);

    int total4 = N * 3 * OUTD * 56;
    k_crop   <<<(total4 + 255) / 256, 256>>>(x, outCrop, total4);
}

// round 5
// speedup vs baseline: 1.8621x; 1.1472x over previous
#include <cuda_runtime.h>

#define NMAX 64
#define OUTD 224
#define HW   50176          // 224*224
#define FC   2048
#define FHW  49             // 7*7
#define RMAX 32             // max runs/row (true bound ~4: rows are piecewise-linear)
#define NRUNS (OUTD * RMAX) // 7168
#define NSLICE 8
#define TMAIN 896           // 4 rows x 224 cols

// global scratch (no allocations allowed)
__device__ float d_part[NMAX * NSLICE * FHW];
__device__ __align__(16) float2 d_tr[NMAX * OUTD];   // per-(n,row): (x0 bits, wx)
__device__ __align__(16) float2 d_tc[NMAX * OUTD];   // per-(n,col): (y0 bits, wy)

// ---------------- union-find over run ids in shared memory ----------------
__device__ __forceinline__ int uf_find(int* P, int i) {
    int p = P[i];
    while (p != i) {
        int gp = P[p];
        if (gp != p) P[i] = gp;   // path halving (benign race)
        i = p; p = gp;
    }
    return i;
}

__device__ __forceinline__ void uf_union(int* P, int a, int b) {
    int ra = uf_find(P, a), rb = uf_find(P, b);
    while (ra != rb) {
        if (ra < rb) { int t = ra; ra = rb; rb = t; }
        int old = atomicCAS(&P[ra], ra, rb);   // link larger root under smaller
        if (old == ra) break;
        ra = uf_find(P, old);
        rb = uf_find(P, rb);
    }
}

// ---------------- kernel 1: per-slice channel-max of |feat| ----------------
// grid (NSLICE, N), block 784: t = cg*49 + p, addr = base + t + 784k (contiguous)
__global__ __launch_bounds__(784) void k_featmax(const float* __restrict__ feat)
{
    __shared__ float sP[16 * FHW];
    const int n = blockIdx.y, s = blockIdx.x;
    const int t = threadIdx.x;
    const float* base = feat + (size_t)n * (FC * FHW) + s * (FC / NSLICE) * FHW + t;
    float m = 0.f;
    #pragma unroll
    for (int k = 0; k < (FC / NSLICE) / 16; k++)   // 16 independent loads
        m = fmaxf(m, fabsf(base[k * 16 * FHW]));
    sP[t] = m;
    __syncthreads();
    if (t < FHW) {
        float mm = sP[t];
        #pragma unroll
        for (int j = 1; j < 16; j++) mm = fmaxf(mm, sP[j * FHW + t]);
        d_part[(n * NSLICE + s) * FHW + t] = mm;
    }
}

// ---------------- kernel 2: normalize + upsample + mask + CCL + bbox + tables ----------------
// one CTA per image; 896 threads = 4 rows x 224 cols (fixed column per thread)
__global__ __launch_bounds__(TMAIN, 1) void k_main(
    float* __restrict__ outHeat,
    float* __restrict__ outCoords)
{
    extern __shared__ int S[];     // sSE[NRUNS], P[NRUNS], cnt[NRUNS]  (86 KB)
    int* sSE = S;
    int* P   = S + NRUNS;
    int* cnt = S + 2 * NRUNS;

    __shared__ float sH[FHW];
    __shared__ int   sX0[OUTD], sX1[OUTD];
    __shared__ float sWt[OUTD];
    __shared__ float sTA[7 * TMAIN];       // hoisted y-interp: sTA[x*896+tid]
    __shared__ unsigned sMask[OUTD * 7];
    __shared__ int   sRunCnt[OUTD];
    __shared__ float sMn, sMx;
    __shared__ int   sBC[28], sBR[28];
    __shared__ int   sBest, sBestCnt, sRmin, sRmax, sCmin, sCmax;
    __shared__ int4  sBox;

    const int n   = blockIdx.x;
    const int tid = threadIdx.x;
    const int row_off = tid / OUTD;        // 0..3
    const int col     = tid - row_off * OUTD;

    // Phase B: gather partial maxes, interp tables, init UF state
    if (tid < FHW) {
        const float* pp = d_part + n * NSLICE * FHW + tid;
        float m = pp[0];
        #pragma unroll
        for (int j = 1; j < NSLICE; j++) m = fmaxf(m, pp[j * FHW]);
        sH[tid] = m;
    }
    if (tid >= 64 && tid < 64 + OUTD) {   // exact reference arithmetic
        int i = tid - 64;
        float g  = (float)i / 223.0f;
        float xs = __fmul_rn(g, 6.0f);
        int x0 = (int)floorf(xs);
        x0 = min(max(x0, 0), 6);
        sX0[i] = x0;
        sX1[i] = min(x0 + 1, 6);
        sWt[i] = __fsub_rn(xs, (float)x0);
    }
    for (int g = tid; g < NRUNS; g += TMAIN) { P[g] = g; cnt[g] = 0; }
    if (tid == 0) { sRmin = HW; sRmax = -1; sCmin = HW; sCmax = -1; }
    __syncthreads();
    if (tid == 0) {
        float mn = sH[0], mx = sH[0];
        for (int j = 1; j < FHW; j++) { mn = fminf(mn, sH[j]); mx = fmaxf(mx, sH[j]); }
        sMn = mn; sMx = mx;
    }
    __syncthreads();
    if (tid < FHW) sH[tid] = (sH[tid] - sMn) / (sMx - sMn);
    __syncthreads();

    // Phase C0: hoist column interpolation (exact inner parenthesis of reference)
    {
        int y0 = sX0[col], y1 = sX1[col];
        float wy = sWt[col], iwy = __fsub_rn(1.f, wy);
        #pragma unroll
        for (int k = 0; k < 7; k++)
            sTA[k * TMAIN + tid] =
                __fadd_rn(__fmul_rn(iwy, sH[k * 7 + y0]), __fmul_rn(wy, sH[k * 7 + y1]));
    }
    __syncthreads();

    // Phase C: row blend, heat write, ballot mask (56 iterations, no div/mod)
    float* oh = outHeat + (size_t)n * HW;
    #pragma unroll 4
    for (int r = row_off; r < OUTD; r += 4) {
        int x0 = sX0[r], x1 = sX1[r];
        float wx = sWt[r];
        float v = __fadd_rn(__fmul_rn(__fsub_rn(1.f, wx), sTA[x0 * TMAIN + tid]),
                            __fmul_rn(wx, sTA[x1 * TMAIN + tid]));
        int o = r * OUTD + col;
        oh[o] = v;
        unsigned m = __ballot_sync(0xffffffffu, v > 0.7f);   // warp = 32-col span of row r
        if ((tid & 31) == 0) sMask[o >> 5] = m;
    }
    __syncthreads();

    // Phase D: per-row run extraction
    if (tid < OUTD) {
        int r = tid, base = r * 7, cntR = 0, pos = 0;
        while (pos < 224 && cntR < RMAX) {
            int w = pos >> 5;
            unsigned m = sMask[base + w] & (0xffffffffu << (pos & 31));
            while (m == 0 && ++w < 7) m = sMask[base + w];
            if (m == 0) break;
            int start = (w << 5) + __ffs(m) - 1;
            unsigned inv = (~sMask[base + w]) & (0xffffffffu << (start & 31));
            int w2 = w;
            while (inv == 0 && ++w2 < 7) inv = ~sMask[base + w2];
            int end = (w2 == 7) ? 223 : ((w2 << 5) + __ffs(inv) - 2);
            sSE[r * RMAX + cntR] = (start << 16) | end;
            cntR++;
            pos = end + 2;
        }
        sRunCnt[r] = cntR;
    }
    __syncthreads();

    // Phase E: union overlapping runs in adjacent rows (8-connectivity)
    if (tid < OUTD - 1) {
        int r = tid;
        int ca = sRunCnt[r], cb = sRunCnt[r + 1];
        int i = 0, j = 0;
        while (i < ca && j < cb) {
            int A = sSE[r * RMAX + i];        int a0 = A >> 16, a1 = A & 0xffff;
            int B = sSE[(r + 1) * RMAX + j];  int b0 = B >> 16, b1 = B & 0xffff;
            if (b0 <= a1 + 1 && a0 <= b1 + 1)
                uf_union(P, r * RMAX + i, (r + 1) * RMAX + j);
            if (a1 <= b1) i++; else j++;
        }
    }
    __syncthreads();

    // Phase F: pixel counts per component (shared atomics)
    for (int g = tid; g < NRUNS; g += TMAIN) {
        int row = g >> 5, slot = g & (RMAX - 1);
        if (slot < sRunCnt[row]) {
            int A = sSE[g];
            atomicAdd(&cnt[uf_find(P, g)], (A & 0xffff) - (A >> 16) + 1);
        }
    }
    __syncthreads();

    // Phase G: argmax (count, tie -> smallest root id == smallest min-pixel-label)
    {
        int bc = 0, br = 0x7fffffff;
        for (int g = tid; g < NRUNS; g += TMAIN) {
            int row = g >> 5, slot = g & (RMAX - 1);
            if (slot < sRunCnt[row]) {
                int cc = cnt[g];
                if (cc > bc || (cc == bc && g < br)) { bc = cc; br = g; }
            }
        }
        #pragma unroll
        for (int off = 16; off; off >>= 1) {
            int oc  = __shfl_down_sync(0xffffffffu, bc, off);
            int orr = __shfl_down_sync(0xffffffffu, br, off);
            if (oc > bc || (oc == bc && orr < br)) { bc = oc; br = orr; }
        }
        if ((tid & 31) == 0) { sBC[tid >> 5] = bc; sBR[tid >> 5] = br; }
        __syncthreads();
        if (tid == 0) {
            bc = sBC[0]; br = sBR[0];
            for (int j = 1; j < TMAIN / 32; j++) {
                if (sBC[j] > bc || (sBC[j] == bc && sBR[j] < br)) { bc = sBC[j]; br = sBR[j]; }
            }
            sBest = br; sBestCnt = bc;
        }
    }
    __syncthreads();

    // Phase H: bbox of largest component
    if (sBestCnt > 0) {
        int best = sBest;
        int rmin = HW, rmax = -1, cmin = HW, cmax = -1;
        for (int g = tid; g < NRUNS; g += TMAIN) {
            int row = g >> 5, slot = g & (RMAX - 1);
            if (slot < sRunCnt[row] && uf_find(P, g) == best) {
                int A = sSE[g];
                rmin = min(rmin, row); rmax = max(rmax, row);
                cmin = min(cmin, A >> 16); cmax = max(cmax, A & 0xffff);
            }
        }
        if (rmax >= 0) {
            atomicMin(&sRmin, rmin); atomicMax(&sRmax, rmax);
            atomicMin(&sCmin, cmin); atomicMax(&sCmax, cmax);
        }
    }
    __syncthreads();

    if (tid == 0) {
        int xmin = sRmin, xmax = sRmax, ymin = sCmin, ymax = sCmax;
        if (sBestCnt <= 0 || xmax < 0) { xmin = 0; ymin = 0; xmax = OUTD - 1; ymax = OUTD - 1; }
        sBox = make_int4(xmin, xmax, ymin, ymax);
        float* co = outCoords + n * 4;
        co[0] = (float)ymin; co[1] = (float)xmin;    // torch order [ymin,xmin,ymax,xmax]
        co[2] = (float)ymax; co[3] = (float)xmax;
    }
    __syncthreads();

    // Phase I: crop interpolation tables
    if (tid < OUTD) {
        int4 bx = sBox;
        int i = tid;
        float g = (float)i / 223.0f;
        int Lx = max(bx.y - bx.x, 1);
        float xs = __fadd_rn((float)bx.x, __fmul_rn(g, (float)(Lx - 1)));
        int x0 = min(max((int)floorf(xs), 0), 223);
        d_tr[n * OUTD + i] = make_float2(__int_as_float(x0), __fsub_rn(xs, (float)x0));
        int Ly = max(bx.w - bx.z, 1);
        float ys = __fadd_rn((float)bx.z, __fmul_rn(g, (float)(Ly - 1)));
        int y0 = min(max((int)floorf(ys), 0), 223);
        d_tc[n * OUTD + i] = make_float2(__int_as_float(y0), __fsub_rn(ys, (float)y0));
    }
}

// ---------------- kernel 3: crop + align-corners bilinear resize (4 outputs/thread) ----------------
__device__ __forceinline__ float bilin1(const float* __restrict__ r0,
                                        const float* __restrict__ r1,
                                        float y0f, float wy, float wx)
{
    int y0 = __float_as_int(y0f);
    int y1 = min(y0 + 1, 223);
    float v00 = __ldg(&r0[y0]), v01 = __ldg(&r0[y1]);
    float v10 = __ldg(&r1[y0]), v11 = __ldg(&r1[y1]);
    float iwy = __fsub_rn(1.f, wy);
    float a = __fadd_rn(__fmul_rn(iwy, v00), __fmul_rn(wy, v01));
    float b = __fadd_rn(__fmul_rn(iwy, v10), __fmul_rn(wy, v11));
    return __fadd_rn(__fmul_rn(__fsub_rn(1.f, wx), a), __fmul_rn(wx, b));
}

__global__ void k_crop(const float* __restrict__ x, float* __restrict__ out, int total4)
{
    int idx = blockIdx.x * blockDim.x + threadIdx.x;
    if (idx >= total4) return;
    int c4 = idx % 56;                 // 4-col group
    int r  = (idx / 56) % OUTD;
    int nc = idx / (56 * OUTD);        // n*3 + ch
    int n  = nc / 3;
    int c0 = c4 * 4;

    float2 tr = d_tr[n * OUTD + r];
    int x0 = __float_as_int(tr.x);
    int x1 = min(x0 + 1, 223);
    float wx = tr.y;

    const float* img  = x + (size_t)nc * HW;
    const float* row0 = img + x0 * OUTD;
    const float* row1 = img + x1 * OUTD;

    const float4* tc4 = reinterpret_cast<const float4*>(d_tc + n * OUTD + c0);
    float4 ta = tc4[0];   // (y0f_a, wy_a, y0f_b, wy_b)
    float4 tb = tc4[1];   // (y0f_c, wy_c, y0f_d, wy_d)

    float4 res;
    res.x = bilin1(row0, row1, ta.x, ta.y, wx);
    res.y = bilin1(row0, row1, ta.z, ta.w, wx);
    res.z = bilin1(row0, row1, tb.x, tb.y, wx);
    res.w = bilin1(row0, row1, tb.z, tb.w, wx);

    *reinterpret_cast<float4*>(out + (size_t)nc * HW + r * OUTD + c0) = res;
}

// ---------------- launch ----------------
extern "C" void kernel_launch(void* const* d_in, const int* in_sizes, int n_in,
                              void* d_out, int out_size)
{
    const float* x    = (const float*)d_in[0];   // (N,3,224,224)
    const float* feat = (const float*)d_in[1];   // (N,2048,7,7)
    float* out = (float*)d_out;

    int N = in_sizes[0] / (3 * HW);
    if (N > NMAX) N = NMAX;

    float* outCrop   = out;
    float* outHeat   = out + (size_t)N * 3 * HW;
    float* outCoords = out + (size_t)N * 3 * HW + (size_t)N * HW;

    static int smemSet = 0;
    if (!smemSet) {
        cudaFuncSetAttribute(k_main, cudaFuncAttributeMaxDynamicSharedMemorySize,
                             3 * NRUNS * (int)sizeof(int));
        smemSet = 1;
    }

    k_featmax<<<dim3(NSLICE, N), 784>>>(feat);
    k_main   <<<N, TMAIN, 3 * NRUNS * sizeof(int)>>>(outHeat, outCoords);

    int total4 = N * 3 * OUTD * 56;
    k_crop   <<<(total4 + 255) / 256, 256>>>(x, outCrop, total4);
}